// round 17
// baseline (speedup 1.0000x reference)
#include <cuda_runtime.h>
#include <math.h>

#define MAXB   4
#define MAXN   16384
#define MAXG   32
#define MAXPB  256
#define MAXAB  128
#define ABLK   128

#ifndef M_PI
#define M_PI 3.14159265358979323846
#endif

// ---------------- device scratch (no allocations allowed) ----------------
__device__ int                  g_lab[MAXB * MAXN];     // PRE-force labels (immutable)
__device__ float                g_mg[MAXB * MAXN * 5];  // PRE-force matched boxes
__device__ unsigned long long   g_best[MAXB * MAXG];
__device__ double               g_part[MAXB * MAXPB];       // focal-neg partials
__device__ double               g_part2[MAXB * MAXPB * 3];  // correction partials
__device__ double               g_part3[MAXB * 3];          // force-delta per image
__device__ int                  g_cnt1[MAXB];
__device__ int                  g_cnt2;
__device__ volatile int         g_bdone[MAXB * MAXAB];      // per-assign-block done

// ---------------- helpers ----------------
__device__ __forceinline__ float jrem180(float x) {
    float r = fmodf(x, 180.0f);
    if (r < 0.0f) r += 180.0f;
    return r;
}

__device__ __forceinline__ float fl_neg(float x) {
    float e     = __expf(-x);
    float denom = 1.0f + e;
    float L     = __logf(denom);
    float inv   = __fdividef(1.0f, denom);
    return 0.75f * inv * inv * (L + x);
}

__device__ __forceinline__ float fl_pos(float x) {
    float e     = __expf(-x);
    float denom = 1.0f + e;
    float L     = __logf(denom);
    float inv   = __fdividef(1.0f, denom);
    float om    = e * inv;
    return 0.25f * om * om * L;
}

__device__ __forceinline__ float reg_loss(const float* ab, const float* mg,
                                          const float* br)
{
    float dlt[5];
    dlt[0] = (mg[0] - ab[0]) / ab[2];
    dlt[1] = (mg[1] - ab[1]) / ab[3];
    dlt[2] = logf(mg[2] / ab[2]);
    dlt[3] = logf(mg[3] / ab[3]);
    dlt[4] = jrem180(mg[4] - ab[4] + 90.0f) - 90.0f;
    float l = 0.0f;
    #pragma unroll
    for (int k = 0; k < 4; k++) {
        float d = fabsf(br[k] - dlt[k]);
        l += (d < 1.0f) ? 0.5f * d * d : d - 0.5f;
    }
    float da = fabsf(jrem180(br[4] - dlt[4] + 90.0f) - 90.0f);
    l += (da < 1.0f) ? 0.5f * da * da : da - 0.5f;
    return l;
}

// register-resident convex quad intersection (edge param-interval form)
__device__ __forceinline__ float arcs_cross_sum(const float* Px, const float* Py,
                                                const float* Qx, const float* Qy)
{
    float acc = 0.0f;
    #pragma unroll
    for (int i = 0; i < 4; i++) {
        int i1 = (i + 1) & 3;
        float ax = Px[i], ay = Py[i];
        float rx = Px[i1] - ax, ry = Py[i1] - ay;
        float p = 0.0f, q = 1.0f;
        float r = 1.0f, s = 1.0f;
        bool empty = false;
        #pragma unroll
        for (int j = 0; j < 4; j++) {
            int j1 = (j + 1) & 3;
            float ex = Qx[j1] - Qx[j], ey = Qy[j1] - Qy[j];
            float d0 = ex * (ay - Qy[j]) - ey * (ax - Qx[j]);
            float d1 = d0 + ex * ry - ey * rx;
            if (d0 < 0.0f) {
                if (d1 < 0.0f) {
                    empty = true;
                } else {
                    float n = -d0, den = d1 - d0;
                    if (n * q > p * den) { p = n; q = den; }
                }
            } else if (d1 < 0.0f) {
                float n = d0, den = d0 - d1;
                if (n * s < r * den) { r = n; s = den; }
            }
        }
        float num = r * q - p * s;
        if (!empty && num > 0.0f)
            acc += num * __fdividef(ax * ry - rx * ay, s * q);
    }
    return acc;
}

__device__ __forceinline__ void make_corners_f(float cx, float cy, float w,
                                               float h, float th,
                                               float* X, float* Y)
{
    float r = th * (float)(M_PI / 180.0);
    float s, c;
    __sincosf(r, &s, &c);
    float lx[4] = {-0.5f * w,  0.5f * w, 0.5f * w, -0.5f * w};
    float ly[4] = {-0.5f * h, -0.5f * h, 0.5f * h,  0.5f * h};
    #pragma unroll
    for (int k = 0; k < 4; k++) {
        X[k] = cx + lx[k] * c - ly[k] * s;
        Y[k] = cy + lx[k] * s + ly[k] * c;
    }
}

// grid-wide finalize (runs in the overall-last block)
__device__ void finalize(float* out, int B, int ablocks)
{
    int t = threadIdx.x;
    __shared__ double df[ABLK], dr[ABLK], dn[ABLK];
    double cls_m = 0.0, reg_m = 0.0;
    for (int bb = 0; bb < B; bb++) {
        double f = 0.0, r = 0.0, n = 0.0;
        for (int k = t; k < ablocks; k += ABLK) {
            f += g_part[bb * MAXPB + k];
            size_t o = (size_t)(bb * MAXPB + k) * 3;
            f += g_part2[o + 0];
            r += g_part2[o + 1];
            n += g_part2[o + 2];
            g_bdone[bb * MAXAB + k] = 0;   // reset for next replay
        }
        df[t] = f; dr[t] = r; dn[t] = n;
        __syncthreads();
        for (int s = ABLK / 2; s > 0; s >>= 1) {
            if (t < s) { df[t] += df[t+s]; dr[t] += dr[t+s]; dn[t] += dn[t+s]; }
            __syncthreads();
        }
        if (t == 0) {
            double f0 = df[0] + g_part3[bb * 3 + 0];
            double r0 = dr[0] + g_part3[bb * 3 + 1];
            double n0 = dn[0] + g_part3[bb * 3 + 2];
            double npos = (n0 < 1.0) ? 1.0 : n0;
            cls_m += f0 / npos;
            reg_m += r0 / npos;
        }
        __syncthreads();
    }
    if (t == 0) {
        cls_m /= (double)B;
        reg_m /= (double)B;
        out[0] = (float)(cls_m + reg_m);
        out[1] = (float)cls_m;
        out[2] = (float)reg_m;
        g_cnt2 = 0;
    }
}

// ---------------- the single kernel ----------------
__global__ __launch_bounds__(ABLK)
void mega_kernel(const float* __restrict__ anchors,
                 const float* __restrict__ gt_boxes,
                 const int*   __restrict__ gt_labels,
                 const float* __restrict__ logits,
                 const float* __restrict__ box_reg,
                 float* __restrict__ out,
                 int N, int G, int C, int B, int ablocks)
{
    int b = blockIdx.y;
    int t = threadIdx.x;
    int total_blocks = (int)(gridDim.x * gridDim.y);

    __shared__ int s_final;
    if (t == 0) s_final = 0;

    // ===== role 2: focal-neg, then per-chunk corrections (pre-force labels)
    if ((int)blockIdx.x >= ablocks) {
        int fb     = blockIdx.x - ablocks;     // chunk id, 1:1 with assign block
        int gtid   = fb * ABLK + t;
        int stride = ablocks * ABLK;
        int E  = N * C;
        int E4 = E >> 2;
        const float4* lp4 = (const float4*)(logits + (size_t)b * E);

        float acc = 0.0f;
        for (int q = gtid; q < E4; q += stride) {
            float4 v = lp4[q];
            acc += fl_neg(v.x) + fl_neg(v.y) + fl_neg(v.z) + fl_neg(v.w);
        }
        for (int e = (E4 << 2) + gtid; e < E; e += stride)
            acc += fl_neg(logits[(size_t)b * E + e]);

        __shared__ float sa[ABLK];
        sa[t] = acc;
        __syncthreads();
        for (int s = ABLK / 2; s > 0; s >>= 1) {
            if (t < s) sa[t] += sa[t + s];
            __syncthreads();
        }
        if (t == 0) g_part[b * MAXPB + fb] = (double)sa[0];

        // wait only for OUR assign chunk's labels
        if (t == 0) {
            while (g_bdone[b * MAXAB + fb] == 0) __nanosleep(100);
        }
        __syncthreads();
        __threadfence();   // acquire chunk labels/mg

        float cf = 0.0f, rl = 0.0f, np = 0.0f;
        int i = fb * ABLK + t;                 // one anchor per thread
        if (i < N) {
            int lab = g_lab[b * MAXN + i];
            if (lab < 0) {
                const float* lp = logits + ((size_t)b * N + i) * (size_t)C;
                float s = 0.0f;
                for (int c = 0; c < C; c++) s += fl_neg(lp[c]);
                cf = -s;
            } else if (lab > 0) {
                float x = logits[((size_t)b * N + i) * (size_t)C + (lab - 1)];
                cf = fl_pos(x) - fl_neg(x);
                np = 1.0f;
                rl = reg_loss(anchors + (size_t)i * 5,
                              &g_mg[(size_t)(b * MAXN + i) * 5],
                              box_reg + ((size_t)b * N + i) * 5);
            }
        }

        __shared__ float sf[ABLK], sr[ABLK], sn[ABLK];
        sf[t] = cf; sr[t] = rl; sn[t] = np;
        __syncthreads();
        for (int s = ABLK / 2; s > 0; s >>= 1) {
            if (t < s) { sf[t] += sf[t+s]; sr[t] += sr[t+s]; sn[t] += sn[t+s]; }
            __syncthreads();
        }
        if (t == 0) {
            size_t o = (size_t)(b * MAXPB + fb) * 3;
            g_part2[o + 0] = (double)sf[0];
            g_part2[o + 1] = (double)sr[0];
            g_part2[o + 2] = (double)sn[0];
            __threadfence();
            int v = atomicAdd(&g_cnt2, 1);
            if (v == total_blocks - 1) s_final = 1;
        }
        __syncthreads();
        if (s_final) finalize(out, B, ablocks);
        return;
    }

    // ================= role 1: assign =================
    int i0 = blockIdx.x * ABLK;
    int i  = i0 + t;
    int lane = t & 31;

    __shared__ float sgx[MAXG][4], sgy[MAXG][4];
    __shared__ float sgb[MAXG][5];
    __shared__ float sg_sz[MAXG];
    __shared__ float sg_area[MAXG];
    __shared__ int   s_gl[MAXG];
    __shared__ unsigned long long s_best[MAXG];
    __shared__ unsigned long long s_bestA[ABLK];
    __shared__ float s_anc[ABLK][5];
    __shared__ float s_acx[ABLK][4], s_acy[ABLK][4];
    __shared__ unsigned short s_q[ABLK * 16];
    __shared__ int   s_qn;
    __shared__ int   s_last;
    __shared__ int   s_bi[MAXG], s_labv[MAXG], s_has[MAXG], s_curmg[MAXG];

    if (t == 0) { s_qn = 0; s_last = 0; }
    if (t < G) {
        const float* gb = gt_boxes + (size_t)(b * G + t) * 5;
        float w = gb[2], h = gb[3];
        #pragma unroll
        for (int k = 0; k < 5; k++) sgb[t][k] = gb[k];
        sg_sz[t]   = fmaxf(w, h);
        sg_area[t] = w * h;
        s_gl[t]    = gt_labels[b * G + t];
        make_corners_f(gb[0], gb[1], w, h, gb[4], sgx[t], sgy[t]);
        s_best[t] = 0ULL;
    }
    s_bestA[t] = 0ULL;
    if (i < N) {
        const float* ab = anchors + (size_t)i * 5;
        #pragma unroll
        for (int k = 0; k < 5; k++) s_anc[t][k] = ab[k];
        make_corners_f(0.0f, 0.0f, ab[2], ab[3], ab[4], s_acx[t], s_acy[t]);
    }
    __syncthreads();

    // phase 1: gate mask -> warp-aggregated queue append
    {
        unsigned mask = 0;
        if (i < N) {
            float ax = s_anc[t][0], ay = s_anc[t][1];
            float a_sz = fmaxf(s_anc[t][2], s_anc[t][3]);
            for (int j = 0; j < G; j++) {
                float dx = ax - sgb[j][0];
                float dy = ay - sgb[j][1];
                float gate = (a_sz + sg_sz[j]) * 0.7f;
                if (sqrtf(dx * dx + dy * dy) < gate) mask |= (1u << j);
            }
        }
        int cnt = __popc(mask);
        int incl = cnt;
        #pragma unroll
        for (int d = 1; d < 32; d <<= 1) {
            int v = __shfl_up_sync(0xFFFFFFFFu, incl, d);
            if (lane >= d) incl += v;
        }
        int wtotal = __shfl_sync(0xFFFFFFFFu, incl, 31);
        int wbase = 0;
        if (lane == 31 && wtotal > 0) wbase = atomicAdd(&s_qn, wtotal);
        wbase = __shfl_sync(0xFFFFFFFFu, wbase, 31);
        int pos = wbase + incl - cnt;
        unsigned m = mask;
        while (m) {
            int j = __ffs(m) - 1;
            m &= m - 1;
            s_q[pos++] = (unsigned short)((t << 5) | j);
        }
    }
    __syncthreads();

    // phase 2: drain queue (register-resident clip)
    int qn = s_qn;
    for (int q = t; q < qn; q += ABLK) {
        int e  = s_q[q];
        int li = e >> 5;
        int j  = e & 31;

        float axc = s_anc[li][0], ayc = s_anc[li][1];
        float pa[4], qa[4], pb[4], qb[4];
        #pragma unroll
        for (int k = 0; k < 4; k++) {
            pa[k] = s_acx[li][k];
            qa[k] = s_acy[li][k];
            pb[k] = sgx[j][k] - axc;
            qb[k] = sgy[j][k] - ayc;
        }
        float inter = 0.5f * (arcs_cross_sum(pa, qa, pb, qb)
                            + arcs_cross_sum(pb, qb, pa, qa));
        float a_area = s_anc[li][2] * s_anc[li][3];
        float iou = inter / (a_area + sg_area[j] - inter + 1e-8f);
        if (iou > 0.0f) {
            unsigned long long ka =
                ((unsigned long long)__float_as_uint(iou) << 32)
                | (unsigned long long)(unsigned)(MAXG - 1 - j);
            atomicMax(&s_bestA[li], ka);
            unsigned long long kg =
                ((unsigned long long)__float_as_uint(iou) << 32)
                | (unsigned long long)(0xFFFFFFFFu - (unsigned)(i0 + li));
            atomicMax(&s_best[j], kg);
        }
    }
    __syncthreads();

    // phase 3: pre-force labels (immutable afterwards)
    if (i < N) {
        unsigned long long ka = s_bestA[t];
        float best_iou = __uint_as_float((unsigned)(ka >> 32));
        int   best_j   = MAXG - 1 - (int)(ka & 31u);
        int lab;
        if (best_iou >= 0.5f) {
            lab = s_gl[best_j] + 1;
            #pragma unroll
            for (int k = 0; k < 5; k++)
                g_mg[(size_t)(b * MAXN + i) * 5 + k] = sgb[best_j][k];
        } else {
            lab = (best_iou < 0.4f) ? 0 : -1;
        }
        g_lab[b * MAXN + i] = lab;
    }
    __syncthreads();

    // release our chunk to the paired correction block
    if (t == 0) {
        __threadfence();
        g_bdone[b * MAXAB + blockIdx.x] = 1;
    }

    if (t < G && s_best[t] != 0ULL)
        atomicMax(&g_best[b * MAXG + t], s_best[t]);

    __syncthreads();
    if (t == 0) {
        __threadfence();
        int v = atomicAdd(&g_cnt1[b], 1);
        if (v == ablocks - 1) s_last = 1;
    }
    __syncthreads();

    // force-match tail: compute DELTA only (g_lab/g_mg stay pre-force)
    if (s_last) {
        if (t == 0) __threadfence();
        __syncthreads();
        if (t < G) {
            unsigned long long key = g_best[b * MAXG + t];
            g_best[b * MAXG + t] = 0ULL;
            int has = (key >> 32) != 0ULL;
            s_has[t] = has;
            int bi = has ? (int)(0xFFFFFFFFu - (unsigned)(key & 0xFFFFFFFFu)) : 0;
            s_bi[t] = bi;
            s_labv[t] = has ? g_lab[b * MAXN + bi] : 0;
            s_curmg[t] = -1;   // -1 = current mg is g_mg[bi] (pre-force)
        }
        __syncthreads();
        if (t == 0) {
            double dcf = 0.0, drl = 0.0, dnp = 0.0;
            for (int j = 0; j < G; j++) {
                if (s_has[j]) {
                    int bi = s_bi[j];
                    int gl = s_gl[j] + 1;
                    int old = s_labv[j];
                    if (old != gl) {
                        const float* lp = logits + ((size_t)b * N + bi) * (size_t)C;
                        const float* ab = anchors + (size_t)bi * 5;
                        const float* br = box_reg + ((size_t)b * N + bi) * 5;
                        // remove old contribution
                        if (old < 0) {
                            float s = 0.0f;
                            for (int c = 0; c < C; c++) s += fl_neg(lp[c]);
                            dcf += (double)s;
                        } else if (old > 0) {
                            float xo = lp[old - 1];
                            dcf -= (double)(fl_pos(xo) - fl_neg(xo));
                            const float* mg_old = (s_curmg[j] >= 0)
                                ? sgb[s_curmg[j]]
                                : &g_mg[(size_t)(b * MAXN + bi) * 5];
                            drl -= (double)reg_loss(ab, mg_old, br);
                            dnp -= 1.0;
                        }
                        // add new contribution
                        float xn = lp[gl - 1];
                        dcf += (double)(fl_pos(xn) - fl_neg(xn));
                        drl += (double)reg_loss(ab, sgb[j], br);
                        dnp += 1.0;
                        // propagate to later GTs forcing the same anchor
                        for (int j2 = j + 1; j2 < G; j2++)
                            if (s_has[j2] && s_bi[j2] == bi) {
                                s_labv[j2] = gl;
                                s_curmg[j2] = j;
                            }
                    }
                }
            }
            g_part3[b * 3 + 0] = dcf;
            g_part3[b * 3 + 1] = drl;
            g_part3[b * 3 + 2] = dnp;
            g_cnt1[b] = 0;
        }
    }
    __syncthreads();

    if (t == 0) {
        __threadfence();
        int v = atomicAdd(&g_cnt2, 1);
        if (v == total_blocks - 1) s_final = 1;
    }
    __syncthreads();
    if (s_final) finalize(out, B, ablocks);
}

// ---------------- launch ----------------
extern "C" void kernel_launch(void* const* d_in, const int* in_sizes, int n_in,
                              void* d_out, int out_size)
{
    const float* logits  = (const float*)d_in[0];
    const float* breg    = (const float*)d_in[1];
    const float* anchors = (const float*)d_in[2];
    const float* gtb     = (const float*)d_in[3];
    const int*   gtl     = (const int*)d_in[4];

    int N = in_sizes[2] / 5;
    int B = in_sizes[1] / (5 * N);
    int C = in_sizes[0] / (B * N);
    int G = in_sizes[4] / B;

    int ablocks = (N + ABLK - 1) / ABLK;

    dim3 mg(2 * ablocks, B);
    mega_kernel<<<mg, ABLK>>>(anchors, gtb, gtl, logits, breg,
                              (float*)d_out, N, G, C, B, ablocks);
}